// round 7
// baseline (speedup 1.0000x reference)
#include <cuda_runtime.h>

#define NDIR   64
#define NBIN   65
#define INV_DH 0.28867513459481287f    // 1/(2*sqrt(3))
#define D_PER  2
#define NGRP   (NDIR / D_PER)          // 32
#define TPB    256
#define NTILE  16                      // 16 blocks x 256 threads = 4096 (j,l) columns
#define NSLOT  NTILE                   // 16 partials per direction
#define SBIN   65
#define NX     262144
#define BIGM   1.0e30f

__device__ float g_part[NDIR * NSLOT * SBIN];

__global__ void dummy_kernel() {}      // parity shim so ncu -s5 captures main_kernel

// Predicated shared reduction: setp + @p red, no BSSY/BSYNC
#define RED_IF_GT(addrv, v, a, b) \
    asm volatile("{ .reg .pred p; setp.gt.f32 p, %2, %3;\n\t" \
                 "@p red.shared.add.f32 [%0], %1; }" \
                 :: "r"(addrv), "f"(v), "f"(a), "f"(b) : "memory")

__device__ __forceinline__ void red_sh(unsigned a, float v) {
    asm volatile("red.shared.add.f32 [%0], %1;" :: "r"(a), "f"(v) : "memory");
}
__device__ __forceinline__ float satfma(float a, float b, float c) {
    float r; asm("fma.rn.sat.f32 %0, %1, %2, %3;" : "=f"(r) : "f"(a), "f"(b), "f"(c));
    return r;
}

__global__ void __launch_bounds__(TPB) main_kernel(const float* __restrict__ x,
                                                   const float* __restrict__ dirs) {
    const int g   = blockIdx.y;
    const int tid = threadIdx.x;
    __shared__ float sh[D_PER][68];
    for (int t = tid; t < D_PER * 68; t += TPB) ((float*)sh)[t] = 0.f;
    __syncthreads();

    const int base = blockIdx.x * TPB + tid;     // (j,l) column
    const int j = base >> 6, l = base & 63;
    const float mj  = (j < 63) ? 1.f : 0.f;
    const float ml  = (l < 63) ? 1.f : 0.f;
    const float mjl = mj * ml;

    // Per-direction state (monotone slot axis: neg-d0 dirs use reversed bins)
    float stepF[D_PER], Fv[D_PER], rs2[D_PER], Tm[D_PER], sgn[D_PER];
    float B1[D_PER], B2[D_PER], B3[D_PER], B4[D_PER], B5[D_PER], B6[D_PER], B7[D_PER];
    float prevtf[D_PER], accLO[D_PER], accHI[D_PER];
    unsigned addr[D_PER];
    #pragma unroll
    for (int d = 0; d < D_PER; d++) {
        int k = g * D_PER + d;
        float d0 = dirs[3*k], d1 = dirs[3*k+1], d2 = dirs[3*k+2];
        float p0 = fmaxf(d0, 0.f), p1 = fmaxf(d1, 0.f), p2 = fmaxf(d2, 0.f);
        float q1 = p0*INV_DH, q2 = p1*INV_DH, q3 = p2*INV_DH;
        float q4 = (p1+p2)*INV_DH, q5 = (p0+p2)*INV_DH;
        float q6 = (p0+p1)*INV_DH, q7 = (p0+p1+p2)*INV_DH;
        float f00 = fmaf(d1*INV_DH, (float)j, fmaf(d2*INV_DH, (float)l, 32.0f));
        if (d0 >= 0.f) {
            stepF[d] = d0*INV_DH;  Fv[d] = f00 + 1.0f;
            sgn[d] = BIGM;  rs2[d] = -1.f;  Tm[d] = 1.f;
            B1[d]=(q1-1.f)*BIGM; B2[d]=(q2-1.f)*BIGM; B3[d]=(q3-1.f)*BIGM;
            B4[d]=(q4-1.f)*BIGM; B5[d]=(q5-1.f)*BIGM; B6[d]=(q6-1.f)*BIGM;
            B7[d]=(q7-1.f)*BIGM;
        } else {
            stepF[d] = -d0*INV_DH; Fv[d] = 64.0f - f00;
            sgn[d] = -BIGM; rs2[d] = 1.f;  Tm[d] = 0.f;
            B1[d]=q1*BIGM; B2[d]=q2*BIGM; B3[d]=q3*BIGM; B4[d]=q4*BIGM;
            B5[d]=q5*BIGM; B6[d]=q6*BIGM; B7[d]=q7*BIGM;
        }
        prevtf[d] = truncf(Fv[d]);
        addr[d] = (unsigned)__cvta_generic_to_shared(&sh[d][0])
                + (((unsigned)(int)prevtf[d]) << 2);
        accLO[d] = 0.f; accHI[d] = 0.f;
    }

    // Software-pipelined stencil: c = plane i, n = plane i+1, prefetch p = i+2.
    // All loads unconditional; out-of-range values are masked by mi/mj/ml,
    // prefetch index clamped in-bounds.
    int idx = base;
    float c00 = x[idx],      c01 = x[idx+1],    c10 = x[idx+64],   c11 = x[idx+65];
    float n00 = x[idx+4096], n01 = x[idx+4097], n10 = x[idx+4160], n11 = x[idx+4161];

    #pragma unroll 4
    for (int ii = 0; ii < 64; ii++) {
        int pidx = idx + 8192;
        pidx = (pidx > NX - 66) ? (NX - 66) : pidx;
        float p00 = x[pidx], p01 = x[pidx+1], p10 = x[pidx+64], p11 = x[pidx+65];

        const float mi = (ii < 63) ? 1.f : 0.f;
        float m_i   = fmaxf(c00, n00);
        float mc    = fmaxf(fmaxf(c00, c01), fmaxf(c10, c11));
        float v_ei  = -m_i * mi;
        float v_ej  = -fmaxf(c00, c10) * mj;
        float v_el  = -fmaxf(c00, c01) * ml;
        float v_fjl = mc * mjl;
        float v_fil = fmaxf(m_i, fmaxf(c01, n01)) * (mi * ml);
        float v_fij = fmaxf(m_i, fmaxf(c10, n10)) * (mi * mj);
        float v_c   = -fmaxf(mc, fmaxf(fmaxf(n00, n01), fmaxf(n10, n11))) * (mi * mjl);
        float T = ((c00 + v_ei) + (v_ej + v_el)) + ((v_fjl + v_fil) + (v_fij + v_c));

        #pragma unroll
        for (int d = 0; d < D_PER; d++) {
            float F  = Fv[d];
            float tf = truncf(F);            // F > 0 always -> trunc == floor
            float fr = F - tf;               // exact
            float m1 = satfma(sgn[d], fr, B1[d]);
            float m2 = satfma(sgn[d], fr, B2[d]);
            float m3 = satfma(sgn[d], fr, B3[d]);
            float m4 = satfma(sgn[d], fr, B4[d]);
            float m5 = satfma(sgn[d], fr, B5[d]);
            float m6 = satfma(sgn[d], fr, B6[d]);
            float m7 = satfma(sgn[d], fr, B7[d]);
            float Sa = fmaf(m1, v_ei, fmaf(m3, v_el, fmaf(m5, v_fil, m7 * v_c)));
            float Sb = fmaf(m2, v_ej, fmaf(m4, v_fjl, m6 * v_fij));
            float S1 = Sa + Sb;
            float cLO = fmaf(rs2[d], S1, Tm[d] * T);   // pos: S0, neg: S1
            float cHI = T - cLO;

            RED_IF_GT(addr[d], accLO[d], tf, prevtf[d]);   // flush on advance
            bool adv = (tf > prevtf[d]);                   // advance is +1 max
            float nLO = adv ? accHI[d] : accLO[d];
            float nHI = adv ? 0.f : accHI[d];
            accLO[d] = nLO + cLO;
            accHI[d] = nHI + cHI;
            addr[d] += adv ? 4u : 0u;
            prevtf[d] = tf;
            Fv[d] = F + stepF[d];
        }

        c00 = n00; c01 = n01; c10 = n10; c11 = n11;
        n00 = p00; n01 = p01; n10 = p10; n11 = p11;
        idx += 4096;
    }

    #pragma unroll
    for (int d = 0; d < D_PER; d++) {
        red_sh(addr[d],      accLO[d]);
        red_sh(addr[d] + 4u, accHI[d]);
    }
    __syncthreads();

    // Writeout (un-reverse neg-d0 directions)
    const int slot = blockIdx.x;
    for (int t = tid; t < D_PER * SBIN; t += TPB) {
        int d = t / SBIN, bin = t - d * SBIN;
        int k = g * D_PER + d;
        int u = (dirs[3*k] < 0.f) ? (65 - bin) : bin;
        g_part[(k * NSLOT + slot) * SBIN + bin] = sh[d][u];
    }
}

// One block per direction: 8 subgroups of 65 threads reduce 2 slots each,
// tree-reduce in shared, then prefix sum.
__global__ void __launch_bounds__(520) finalize(float* __restrict__ out) {
    const int k   = blockIdx.x;
    const int tid = threadIdx.x;
    const int sub = tid / NBIN;
    const int bin = tid - sub * NBIN;
    __shared__ float red[8][NBIN];

    float acc = 0.f;
    const float* p = &g_part[k * NSLOT * SBIN + bin];
    #pragma unroll
    for (int s = 0; s < NSLOT / 8; s++)
        acc += p[(sub * (NSLOT / 8) + s) * SBIN];
    red[sub][bin] = acc;
    __syncthreads();

    if (sub == 0) {
        float t = 0.f;
        #pragma unroll
        for (int r = 0; r < 8; r++) t += red[r][bin];
        red[0][bin] = t;
    }
    __syncthreads();
    if (sub == 0) {
        float a = 0.f;
        for (int b = 0; b <= bin; b++) a += red[0][b];
        out[k * NBIN + bin] = a;
    }
}

extern "C" void kernel_launch(void* const* d_in, const int* in_sizes, int n_in,
                              void* d_out, int out_size) {
    const float* x    = (const float*)d_in[0];
    const float* dirs = (const float*)d_in[1];
    float* out = (float*)d_out;

    dummy_kernel<<<1, 32>>>();                          // parity shim (ncu -s5 -> main)
    main_kernel<<<dim3(NTILE, NGRP), TPB>>>(x, dirs);
    finalize<<<NDIR, 520>>>(out);
    dummy_kernel<<<1, 32>>>();                          // parity shim
}